// round 15
// baseline (speedup 1.0000x reference)
#include <cuda_runtime.h>
#include <cuda_bf16.h>
#include <math.h>
#include <stdint.h>

#define BATCH 1024
#define FRAMES 31
#define NFFT 2048
#define N2 1024            // packed complex FFT length
#define KF 1152            // folded K: 1025 padded to 3*384
#define HID 256
#define K2C 768            // gemm2 concatenated K: [h|l|h] x [wh|wh|wl]
#define NZ1 9              // gemm1 z: 3 terms x 3 k-chunks
#define NZ2 6              // gemm2 z: 6 k-chunks of 128
#define ASTR 40            // smem row stride (bf16 elems): 32 + 8 pad

#define RPB 4              // batch rows per fft block (software pipeline)
#define FBLK (BATCH / RPB) // 256 fft blocks
#define W1BLKS 288         // HID*KF / 1024 elems-per-block
#define W2BLKS 64          // HID*HID / 1024

// Scratch (allocation-free rule: __device__ globals)
__device__ __align__(16) __nv_bfloat16 g_a_h[BATCH * KF];
__device__ __align__(16) __nv_bfloat16 g_a_l[BATCH * KF];
__device__ __align__(16) __nv_bfloat16 g_w_h[HID * KF];
__device__ __align__(16) __nv_bfloat16 g_w_l[HID * KF];
__device__ __align__(16) __nv_bfloat16 g_w2c[HID * K2C];
__device__ __align__(16) __nv_bfloat16 g_h1c[BATCH * K2C];
__device__ __align__(16) float g_p1[NZ1][BATCH * HID];
__device__ __align__(16) float g_p2[NZ2][BATCH * HID];

// ---------------------------------------------------------------------------
// helpers
// ---------------------------------------------------------------------------
__device__ __forceinline__ uint32_t s2u(const void* p) {
    uint32_t a;
    asm("{ .reg .u64 t; cvta.to.shared.u64 t, %1; cvt.u32.u64 %0, t; }"
        : "=r"(a) : "l"(p));
    return a;
}
__device__ __forceinline__ void ldsm4(uint32_t& r0, uint32_t& r1, uint32_t& r2,
                                      uint32_t& r3, uint32_t addr) {
    asm volatile("ldmatrix.sync.aligned.m8n8.x4.shared.b16 {%0,%1,%2,%3}, [%4];"
                 : "=r"(r0), "=r"(r1), "=r"(r2), "=r"(r3) : "r"(addr));
}
__device__ __forceinline__ void mma_bf16(float* d, const uint32_t* a, const uint32_t* b) {
    asm volatile(
        "mma.sync.aligned.m16n8k16.row.col.f32.bf16.bf16.f32 "
        "{%0,%1,%2,%3}, {%4,%5,%6,%7}, {%8,%9}, {%0,%1,%2,%3};"
        : "+f"(d[0]), "+f"(d[1]), "+f"(d[2]), "+f"(d[3])
        : "r"(a[0]), "r"(a[1]), "r"(a[2]), "r"(a[3]), "r"(b[0]), "r"(b[1]));
}
__device__ __forceinline__ void bf_split(float v, __nv_bfloat16& h, __nv_bfloat16& l) {
    h = __float2bfloat16(v);
    l = __float2bfloat16(v - __bfloat162float(h));
}
__device__ __forceinline__ float2 cmul(float2 a, float2 b) {
    return make_float2(a.x * b.x - a.y * b.y, a.x * b.y + a.y * b.x);
}

// ---------------------------------------------------------------------------
// Fused kernel.
//  blocks [0, FBLK)        : 4 batch rows each, pipelined mean+FFT+untangle
//  blocks [FBLK, +W1BLKS)  : W1 fold + hi/lo split
//  blocks [.., +W2BLKS)    : W2 split -> concatenated layout
// While FFT-ing row i, the mean-loads of row i+1 are interleaved between the
// radix-4 stages so DRAM stays busy through the compute phase.
// ---------------------------------------------------------------------------
__device__ __forceinline__ unsigned rev4_10(unsigned j) {
    unsigned r = __brev(j) >> 22;
    return ((r & 0x155u) << 1) | ((r >> 1) & 0x155u);
}

__global__ __launch_bounds__(256) void fftmean_prep_kernel(
    const float* __restrict__ x,
    const float* __restrict__ W1, const float* __restrict__ W2)
{
    __shared__ float2 s[N2];        // 8 KB
    __shared__ float2 tw[N2];       // 8 KB
    __shared__ float2 c32[32], C32[32], uf32[32], Uc17[17];

    const int tid = threadIdx.x;

    if (blockIdx.x >= FBLK) {
        const int wb = blockIdx.x - FBLK;
        if (wb < W1BLKS) {
            const int idx4 = wb * 1024 + tid * 4;
            const int n = idx4 / KF;
            const int k0 = idx4 - n * KF;
            __nv_bfloat16 h[4], l[4];
            #pragma unroll
            for (int j = 0; j < 4; j++) {
                const int k = k0 + j;
                float v;
                if (k == 0)         v = W1[(size_t)n * NFFT];
                else if (k < 1024)  v = W1[(size_t)n * NFFT + k]
                                      + W1[(size_t)n * NFFT + (NFFT - k)];
                else if (k == 1024) v = W1[(size_t)n * NFFT + 1024];
                else                v = 0.f;
                bf_split(v, h[j], l[j]);
            }
            *(uint2*)&g_w_h[idx4] = *(uint2*)h;
            *(uint2*)&g_w_l[idx4] = *(uint2*)l;
        } else {
            const int idx4 = (wb - W1BLKS) * 1024 + tid * 4;
            const int n = idx4 >> 8;
            const int k = idx4 & 255;
            const float4 v = *(const float4*)&W2[idx4];
            __nv_bfloat16 h[4], l[4];
            bf_split(v.x, h[0], l[0]); bf_split(v.y, h[1], l[1]);
            bf_split(v.z, h[2], l[2]); bf_split(v.w, h[3], l[3]);
            const int base = n * K2C + k;
            *(uint2*)&g_w2c[base]       = *(uint2*)h;
            *(uint2*)&g_w2c[base + 256] = *(uint2*)h;
            *(uint2*)&g_w2c[base + 512] = *(uint2*)l;
        }
        return;
    }

    // base trig tables: 113 sincosf per block (amortized over 4 rows)
    if (tid < 32) {
        float sv, cv;
        sincosf(-6.28318530717958647692f * (float)tid * (1.0f / 1024.0f), &sv, &cv);
        c32[tid] = make_float2(cv, sv);
    } else if (tid < 64) {
        const int j = tid - 32;
        float sv, cv;
        sincosf(-6.28318530717958647692f * (float)j * (1.0f / 32.0f), &sv, &cv);
        C32[j] = make_float2(cv, sv);
    } else if (tid < 96) {
        const int j = tid - 64;
        float sv, cv;
        sincosf(3.14159265358979323846f * (float)j * (1.0f / 1024.0f), &sv, &cv);
        uf32[j] = make_float2(cv, sv);
    } else if (tid < 113) {
        const int j = tid - 96;
        float sv, cv;
        sincosf(3.14159265358979323846f * (float)j * (1.0f / 32.0f), &sv, &cv);
        Uc17[j] = make_float2(cv, sv);
    }
    __syncthreads();
    #pragma unroll
    for (int a = tid; a < N2; a += 256)
        tw[a] = cmul(C32[a >> 5], c32[a & 31]);
    // tw visible after the first in-loop barrier below

    const int b0 = blockIdx.x * RPB;
    const float4* __restrict__ xb = (const float4*)x;
    const int f0 = tid, f1 = tid + 256;
    const float inv = 1.0f / FRAMES;

    // prologue: mean-load row b0
    float4 a0 = make_float4(0.f, 0.f, 0.f, 0.f);
    float4 a1 = make_float4(0.f, 0.f, 0.f, 0.f);
    {
        const float4* p = xb + (size_t)b0 * (FRAMES * NFFT / 4);
        #pragma unroll
        for (int t = 0; t < FRAMES; t++) {
            float4 v0 = p[f0 + t * (NFFT / 4)];
            float4 v1 = p[f1 + t * (NFFT / 4)];
            a0.x += v0.x; a0.y += v0.y; a0.z += v0.z; a0.w += v0.w;
            a1.x += v1.x; a1.y += v1.y; a1.z += v1.z; a1.w += v1.w;
        }
    }

    #pragma unroll 1
    for (int i = 0; i < RPB; i++) {
        __syncthreads();   // previous row's untangle reads done; also fences tw build
        s[rev4_10(2 * f0)]     = make_float2(a0.x * inv, a0.y * inv);
        s[rev4_10(2 * f0 + 1)] = make_float2(a0.z * inv, a0.w * inv);
        s[rev4_10(2 * f1)]     = make_float2(a1.x * inv, a1.y * inv);
        s[rev4_10(2 * f1 + 1)] = make_float2(a1.z * inv, a1.w * inv);
        __syncthreads();

        const bool more = (i + 1 < RPB);
        const float4* __restrict__ pn = more
            ? xb + (size_t)(b0 + i + 1) * (FRAMES * NFFT / 4) : (const float4*)0;
        float4 n0 = make_float4(0.f, 0.f, 0.f, 0.f);
        float4 n1 = make_float4(0.f, 0.f, 0.f, 0.f);

        // 5 radix-4 stages; next row's mean-loads interleaved per stage
        #pragma unroll
        for (int st = 0; st < 5; st++) {
            if (more) {
                const int t0 = st * 7;
                const int t1 = (t0 + 7 < FRAMES) ? t0 + 7 : FRAMES;
                #pragma unroll
                for (int tt = t0; tt < t1; tt++) {
                    float4 v0 = pn[f0 + tt * (NFFT / 4)];
                    float4 v1 = pn[f1 + tt * (NFFT / 4)];
                    n0.x += v0.x; n0.y += v0.y; n0.z += v0.z; n0.w += v0.w;
                    n1.x += v1.x; n1.y += v1.y; n1.z += v1.z; n1.w += v1.w;
                }
            }
            const int q    = 1 << (2 * st);
            const int j    = tid & (q - 1);
            const int blk  = tid >> (2 * st);
            const int base = (blk << (2 * st + 2)) + j;
            const int e    = j << (8 - 2 * st);

            float2 x0 = s[base];
            float2 x1 = s[base + q];
            float2 x2 = s[base + 2 * q];
            float2 x3 = s[base + 3 * q];
            if (e) {
                x1 = cmul(x1, tw[e]);
                x2 = cmul(x2, tw[2 * e]);
                x3 = cmul(x3, tw[3 * e]);
            }
            const float2 ap = make_float2(x0.x + x2.x, x0.y + x2.y);
            const float2 am = make_float2(x0.x - x2.x, x0.y - x2.y);
            const float2 bp = make_float2(x1.x + x3.x, x1.y + x3.y);
            const float2 bm = make_float2(x1.x - x3.x, x1.y - x3.y);
            s[base]         = make_float2(ap.x + bp.x, ap.y + bp.y);
            s[base + q]     = make_float2(am.x + bm.y, am.y - bm.x);
            s[base + 2 * q] = make_float2(ap.x - bp.x, ap.y - bp.y);
            s[base + 3 * q] = make_float2(am.x - bm.y, am.y + bm.x);
            __syncthreads();
        }

        // untangle + bf16 hi/lo store for row b0+i
        __nv_bfloat16* __restrict__ oh = g_a_h + (size_t)(b0 + i) * KF;
        __nv_bfloat16* __restrict__ ol = g_a_l + (size_t)(b0 + i) * KF;
        #pragma unroll
        for (int k = tid; k <= N2 / 2; k += 256) {
            const float2 zk = s[k];
            const float2 z2 = s[(N2 - k) & (N2 - 1)];
            const float2 u  = cmul(Uc17[k >> 5], uf32[k & 31]);
            const float sumr = zk.x + z2.x;
            const float sumi = zk.y + z2.y;
            const float difr = zk.x - z2.x;
            float v0 = 0.5f * (sumr + u.x * sumi - u.y * difr);
            float v1 = 0.5f * (sumr - u.x * sumi + u.y * difr);
            __nv_bfloat16 h, l;
            bf_split(v0, h, l); oh[k] = h;       ol[k] = l;
            bf_split(v1, h, l); oh[N2 - k] = h;  ol[N2 - k] = l;
        }
        const __nv_bfloat16 z16 = __float2bfloat16(0.f);
        for (int k = N2 + 1 + tid; k < KF; k += 256) { oh[k] = z16; ol[k] = z16; }

        a0 = n0;
        a1 = n1;
    }
}

// ---------------------------------------------------------------------------
// GEMM1: bf16 mma (hi/lo 3-term), BM=128, BN=128, BK=32, 256 thr, 8 warps.
// ---------------------------------------------------------------------------
__global__ __launch_bounds__(256, 2) void gemm1_mma_kernel(
    const __nv_bfloat16* __restrict__ Ah, const __nv_bfloat16* __restrict__ Al,
    const __nv_bfloat16* __restrict__ Wh, const __nv_bfloat16* __restrict__ Wl)
{
    const int KS = KF, KITERS = 12, KSPL = 3;
    __shared__ __nv_bfloat16 As[2][128 * ASTR];   // 20 KB
    __shared__ __nv_bfloat16 Bs[2][128 * ASTR];   // 20 KB

    const int tid  = threadIdx.x;
    const int wid  = tid >> 5;
    const int lane = tid & 31;
    const int wm0  = (wid & 1) * 64;
    const int wn0  = (wid >> 1) * 32;
    const int m0   = blockIdx.x * 128;
    const int n0   = blockIdx.y * 128;
    const int z    = blockIdx.z;
    const int term = z / KSPL;
    const int kbeg = (z - term * KSPL) * (KITERS * 32);

    const __nv_bfloat16* __restrict__ A = (term == 1) ? Al : Ah;
    const __nv_bfloat16* __restrict__ W = (term == 2) ? Wl : Wh;

    const int a_row = (lane & 7) + ((lane >> 3) & 1) * 8;
    const int a_col = (lane >> 4) * 8;
    const int b_row = ((lane >> 4) & 1) * 8 + (lane & 7);
    const int b_col = ((lane >> 3) & 1) * 8;

    float acc[4][4][4] = {};
    uint4 rA[2], rB[2];

    #pragma unroll
    for (int i = 0; i < 2; i++) {
        const int c   = tid + i * 256;
        const int row = c >> 2;
        const int cc  = (c & 3) * 8;
        *(uint4*)&As[0][row * ASTR + cc] =
            *(const uint4*)&A[(size_t)(m0 + row) * KS + kbeg + cc];
        *(uint4*)&Bs[0][row * ASTR + cc] =
            *(const uint4*)&W[(size_t)(n0 + row) * KS + kbeg + cc];
    }

    #pragma unroll 1
    for (int it = 0; it < KITERS; it++) {
        const int cur = it & 1;
        __syncthreads();
        if (it + 1 < KITERS) {
            const int k0 = kbeg + (it + 1) * 32;
            #pragma unroll
            for (int i = 0; i < 2; i++) {
                const int c   = tid + i * 256;
                const int row = c >> 2;
                const int cc  = (c & 3) * 8;
                rA[i] = *(const uint4*)&A[(size_t)(m0 + row) * KS + k0 + cc];
                rB[i] = *(const uint4*)&W[(size_t)(n0 + row) * KS + k0 + cc];
            }
        }

        const uint32_t baseA = s2u(&As[cur][0]);
        const uint32_t baseB = s2u(&Bs[cur][0]);
        #pragma unroll
        for (int kk = 0; kk < 2; kk++) {
            uint32_t bfr[4][2];
            #pragma unroll
            for (int np = 0; np < 2; np++) {
                uint32_t r0, r1, r2, r3;
                uint32_t addr = baseB +
                    (uint32_t)(((wn0 + np * 16 + b_row) * ASTR + kk * 16 + b_col) * 2);
                ldsm4(r0, r1, r2, r3, addr);
                bfr[np * 2][0] = r0;     bfr[np * 2][1] = r1;
                bfr[np * 2 + 1][0] = r2; bfr[np * 2 + 1][1] = r3;
            }
            #pragma unroll
            for (int mi = 0; mi < 4; mi++) {
                uint32_t afr[4];
                uint32_t addr = baseA +
                    (uint32_t)(((wm0 + mi * 16 + a_row) * ASTR + kk * 16 + a_col) * 2);
                ldsm4(afr[0], afr[1], afr[2], afr[3], addr);
                #pragma unroll
                for (int ni = 0; ni < 4; ni++)
                    mma_bf16(acc[mi][ni], afr, bfr[ni]);
            }
        }

        if (it + 1 < KITERS) {
            const int nxt = cur ^ 1;
            #pragma unroll
            for (int i = 0; i < 2; i++) {
                const int c   = tid + i * 256;
                const int row = c >> 2;
                const int cc  = (c & 3) * 8;
                *(uint4*)&As[nxt][row * ASTR + cc] = rA[i];
                *(uint4*)&Bs[nxt][row * ASTR + cc] = rB[i];
            }
        }
    }

    float* __restrict__ P = g_p1[z];
    const int t4 = lane >> 2;
    const int t2 = (lane & 3) * 2;
    #pragma unroll
    for (int mi = 0; mi < 4; mi++) {
        const int row = m0 + wm0 + mi * 16 + t4;
        #pragma unroll
        for (int ni = 0; ni < 4; ni++) {
            const int col = n0 + wn0 + ni * 8 + t2;
            *(float2*)&P[(size_t)row * HID + col] =
                make_float2(acc[mi][ni][0], acc[mi][ni][1]);
            *(float2*)&P[(size_t)(row + 8) * HID + col] =
                make_float2(acc[mi][ni][2], acc[mi][ni][3]);
        }
    }
}

// ---------------------------------------------------------------------------
// GEMM2: concatenated K=768, chunk 128 (4 iters), split-K 6.
// BM=64, BN=64, BK=32, 128 threads, grid (16,4,6) = 384 CTAs.
// ---------------------------------------------------------------------------
__global__ __launch_bounds__(128) void gemm2_mma_kernel() {
    const int KITERS = 4;
    __shared__ __nv_bfloat16 As[2][64 * ASTR];   // 10 KB
    __shared__ __nv_bfloat16 Bs[2][64 * ASTR];   // 10 KB

    const int tid  = threadIdx.x;
    const int wid  = tid >> 5;
    const int lane = tid & 31;
    const int wm0  = (wid & 1) * 32;
    const int wn0  = (wid >> 1) * 32;
    const int m0   = blockIdx.x * 64;
    const int n0   = blockIdx.y * 64;
    const int kbeg = blockIdx.z * 128;

    const int a_row = (lane & 7) + ((lane >> 3) & 1) * 8;
    const int a_col = (lane >> 4) * 8;
    const int b_row = ((lane >> 4) & 1) * 8 + (lane & 7);
    const int b_col = ((lane >> 3) & 1) * 8;

    float acc[2][4][4] = {};
    uint4 rA[2], rB[2];

    #pragma unroll
    for (int i = 0; i < 2; i++) {
        const int c   = tid + i * 128;
        const int row = c >> 2;
        const int cc  = (c & 3) * 8;
        *(uint4*)&As[0][row * ASTR + cc] =
            *(const uint4*)&g_h1c[(size_t)(m0 + row) * K2C + kbeg + cc];
        *(uint4*)&Bs[0][row * ASTR + cc] =
            *(const uint4*)&g_w2c[(size_t)(n0 + row) * K2C + kbeg + cc];
    }

    #pragma unroll 1
    for (int it = 0; it < KITERS; it++) {
        const int cur = it & 1;
        __syncthreads();
        if (it + 1 < KITERS) {
            const int k0 = kbeg + (it + 1) * 32;
            #pragma unroll
            for (int i = 0; i < 2; i++) {
                const int c   = tid + i * 128;
                const int row = c >> 2;
                const int cc  = (c & 3) * 8;
                rA[i] = *(const uint4*)&g_h1c[(size_t)(m0 + row) * K2C + k0 + cc];
                rB[i] = *(const uint4*)&g_w2c[(size_t)(n0 + row) * K2C + k0 + cc];
            }
        }

        const uint32_t baseA = s2u(&As[cur][0]);
        const uint32_t baseB = s2u(&Bs[cur][0]);
        #pragma unroll
        for (int kk = 0; kk < 2; kk++) {
            uint32_t bfr[4][2];
            #pragma unroll
            for (int np = 0; np < 2; np++) {
                uint32_t r0, r1, r2, r3;
                uint32_t addr = baseB +
                    (uint32_t)(((wn0 + np * 16 + b_row) * ASTR + kk * 16 + b_col) * 2);
                ldsm4(r0, r1, r2, r3, addr);
                bfr[np * 2][0] = r0;     bfr[np * 2][1] = r1;
                bfr[np * 2 + 1][0] = r2; bfr[np * 2 + 1][1] = r3;
            }
            #pragma unroll
            for (int mi = 0; mi < 2; mi++) {
                uint32_t afr[4];
                uint32_t addr = baseA +
                    (uint32_t)(((wm0 + mi * 16 + a_row) * ASTR + kk * 16 + a_col) * 2);
                ldsm4(afr[0], afr[1], afr[2], afr[3], addr);
                #pragma unroll
                for (int ni = 0; ni < 4; ni++)
                    mma_bf16(acc[mi][ni], afr, bfr[ni]);
            }
        }

        if (it + 1 < KITERS) {
            const int nxt = cur ^ 1;
            #pragma unroll
            for (int i = 0; i < 2; i++) {
                const int c   = tid + i * 128;
                const int row = c >> 2;
                const int cc  = (c & 3) * 8;
                *(uint4*)&As[nxt][row * ASTR + cc] = rA[i];
                *(uint4*)&Bs[nxt][row * ASTR + cc] = rB[i];
            }
        }
    }

    float* __restrict__ P = g_p2[blockIdx.z];
    const int t4 = lane >> 2;
    const int t2 = (lane & 3) * 2;
    #pragma unroll
    for (int mi = 0; mi < 2; mi++) {
        const int row = m0 + wm0 + mi * 16 + t4;
        #pragma unroll
        for (int ni = 0; ni < 4; ni++) {
            const int col = n0 + wn0 + ni * 8 + t2;
            *(float2*)&P[(size_t)row * HID + col] =
                make_float2(acc[mi][ni][0], acc[mi][ni][1]);
            *(float2*)&P[(size_t)(row + 8) * HID + col] =
                make_float2(acc[mi][ni][2], acc[mi][ni][3]);
        }
    }
}

// ---------------------------------------------------------------------------
// Reduce gemm1 partials + bias + relu -> h1cat [h | l | h].  float2/thread.
// ---------------------------------------------------------------------------
__global__ __launch_bounds__(256) void reduce1_kernel(const float* __restrict__ bias) {
    const int i2 = blockIdx.x * 256 + threadIdx.x;     // 0 .. 131071
    const int n2 = i2 & (HID / 2 - 1);
    const int row = i2 >> 7;
    float2 v = ((const float2*)bias)[n2];
    #pragma unroll
    for (int zz = 0; zz < NZ1; zz++) {
        const float2 pv = *(const float2*)&g_p1[zz][i2 * 2];
        v.x += pv.x; v.y += pv.y;
    }
    v.x = fmaxf(v.x, 0.f);
    v.y = fmaxf(v.y, 0.f);
    __nv_bfloat16 h[2], l[2];
    bf_split(v.x, h[0], l[0]);
    bf_split(v.y, h[1], l[1]);
    const int base = row * K2C + n2 * 2;
    *(uint32_t*)&g_h1c[base]       = *(uint32_t*)h;
    *(uint32_t*)&g_h1c[base + 256] = *(uint32_t*)l;
    *(uint32_t*)&g_h1c[base + 512] = *(uint32_t*)h;
}

// ---------------------------------------------------------------------------
// Fused: reduce gemm2 partials (6) + bias + relu + dot(W3) + sigmoid -> out.
// ---------------------------------------------------------------------------
__global__ __launch_bounds__(256) void reduce2_out_kernel(
    const float* __restrict__ b2, const float* __restrict__ W3,
    const float* __restrict__ b3, float* __restrict__ out)
{
    const int warp = threadIdx.x >> 5;
    const int lane = threadIdx.x & 31;
    const int b    = blockIdx.x * 8 + warp;
    const int base = b * HID + lane * 8;

    float s = 0.f;
    #pragma unroll
    for (int half = 0; half < 2; half++) {
        const int off = base + half * 4;
        const int coff = lane * 8 + half * 4;
        float4 v  = *(const float4*)&b2[coff];
        #pragma unroll
        for (int zz = 0; zz < NZ2; zz++) {
            const float4 pv = *(const float4*)&g_p2[zz][off];
            v.x += pv.x; v.y += pv.y; v.z += pv.z; v.w += pv.w;
        }
        const float4 w = *(const float4*)&W3[coff];
        s += fmaxf(v.x, 0.f) * w.x + fmaxf(v.y, 0.f) * w.y
           + fmaxf(v.z, 0.f) * w.z + fmaxf(v.w, 0.f) * w.w;
    }
    #pragma unroll
    for (int off = 16; off; off >>= 1) s += __shfl_down_sync(0xffffffffu, s, off);
    if (lane == 0) out[b] = 1.f / (1.f + expf(-(s + b3[0])));
}

// ---------------------------------------------------------------------------
extern "C" void kernel_launch(void* const* d_in, const int* in_sizes, int n_in,
                              void* d_out, int out_size)
{
    const float* x  = (const float*)d_in[0];
    const float* W1 = (const float*)d_in[1];
    const float* b1 = (const float*)d_in[2];
    const float* W2 = (const float*)d_in[3];
    const float* b2 = (const float*)d_in[4];
    const float* W3 = (const float*)d_in[5];
    const float* b3 = (const float*)d_in[6];
    float* out = (float*)d_out;

    __nv_bfloat16 *p_ah, *p_al, *p_wh, *p_wl;
    cudaGetSymbolAddress((void**)&p_ah, g_a_h);
    cudaGetSymbolAddress((void**)&p_al, g_a_l);
    cudaGetSymbolAddress((void**)&p_wh, g_w_h);
    cudaGetSymbolAddress((void**)&p_wl, g_w_l);

    // launch 1: pipelined FFT blocks (256) + W1 fold/split (288) + W2 split/cat (64)
    fftmean_prep_kernel<<<FBLK + W1BLKS + W2BLKS, 256>>>(x, W1, W2);

    // launch 2: gemm1 (K=1152, 3 terms x 3 chunks)
    dim3 g1(BATCH / 128, HID / 128, NZ1);    // (8, 2, 9) = 144 CTAs
    gemm1_mma_kernel<<<g1, 256>>>(p_ah, p_al, p_wh, p_wl);

    // launch 3: reduce1 -> h1cat
    reduce1_kernel<<<BATCH * HID / 2 / 256, 256>>>(b1);

    // launch 4: gemm2 (K=768 concat, split-K 6) = 384 CTAs
    dim3 g2(BATCH / 64, HID / 64, NZ2);
    gemm2_mma_kernel<<<g2, 128>>>();

    // launch 5: reduce2 + dot(W3) + sigmoid
    reduce2_out_kernel<<<BATCH / 8, 256>>>(b2, W3, b3, out);
}

// round 16
// speedup vs baseline: 1.2000x; 1.2000x over previous
#include <cuda_runtime.h>
#include <cuda_bf16.h>
#include <math.h>
#include <stdint.h>

#define BATCH 1024
#define FRAMES 31
#define NFFT 2048
#define N2 1024            // packed complex FFT length
#define KF 1152            // folded K: 1025 padded to 3*384
#define HID 256
#define K2C 768            // gemm2 concatenated K: [h|l|h] x [wh|wh|wl]
#define NZ1 9              // gemm1 z: 3 terms x 3 k-chunks
#define NZ2 6              // gemm2 z: 6 k-chunks of 128
#define ASTR 40            // gemm1 smem row stride (bf16): 32 + 8 pad
#define ASTR2 136          // gemm2 smem row stride (bf16): 128 + 8 pad

#define W1BLKS 288         // HID*KF / 1024 elems-per-block
#define W2BLKS 64          // HID*HID / 1024

// Scratch (allocation-free rule: __device__ globals)
__device__ __align__(16) __nv_bfloat16 g_a_h[BATCH * KF];
__device__ __align__(16) __nv_bfloat16 g_a_l[BATCH * KF];
__device__ __align__(16) __nv_bfloat16 g_w_h[HID * KF];
__device__ __align__(16) __nv_bfloat16 g_w_l[HID * KF];
__device__ __align__(16) __nv_bfloat16 g_w2c[HID * K2C];
__device__ __align__(16) __nv_bfloat16 g_h1c[BATCH * K2C];
__device__ __align__(16) float g_p1[NZ1][BATCH * HID];
__device__ __align__(16) float g_p2[NZ2][BATCH * HID];

// ---------------------------------------------------------------------------
// helpers
// ---------------------------------------------------------------------------
__device__ __forceinline__ uint32_t s2u(const void* p) {
    uint32_t a;
    asm("{ .reg .u64 t; cvta.to.shared.u64 t, %1; cvt.u32.u64 %0, t; }"
        : "=r"(a) : "l"(p));
    return a;
}
__device__ __forceinline__ void ldsm4(uint32_t& r0, uint32_t& r1, uint32_t& r2,
                                      uint32_t& r3, uint32_t addr) {
    asm volatile("ldmatrix.sync.aligned.m8n8.x4.shared.b16 {%0,%1,%2,%3}, [%4];"
                 : "=r"(r0), "=r"(r1), "=r"(r2), "=r"(r3) : "r"(addr));
}
__device__ __forceinline__ void mma_bf16(float* d, const uint32_t* a, const uint32_t* b) {
    asm volatile(
        "mma.sync.aligned.m16n8k16.row.col.f32.bf16.bf16.f32 "
        "{%0,%1,%2,%3}, {%4,%5,%6,%7}, {%8,%9}, {%0,%1,%2,%3};"
        : "+f"(d[0]), "+f"(d[1]), "+f"(d[2]), "+f"(d[3])
        : "r"(a[0]), "r"(a[1]), "r"(a[2]), "r"(a[3]), "r"(b[0]), "r"(b[1]));
}
__device__ __forceinline__ void bf_split(float v, __nv_bfloat16& h, __nv_bfloat16& l) {
    h = __float2bfloat16(v);
    l = __float2bfloat16(v - __bfloat162float(h));
}

// ---------------------------------------------------------------------------
// Fused kernel: blocks [0,1024) = frame-mean + radix-4 rFFT + untangle;
// blocks [1024,1312) = W1 fold+split; blocks [1312,1376) = W2 split->cat.
// (Exact R12/78.5us-measured form: in-kernel sincosf, no pipelining.)
// ---------------------------------------------------------------------------
__device__ __forceinline__ unsigned rev4_10(unsigned j) {
    unsigned r = __brev(j) >> 22;
    return ((r & 0x155u) << 1) | ((r >> 1) & 0x155u);
}

__global__ __launch_bounds__(256, 3) void fftmean_prep_kernel(
    const float* __restrict__ x,
    const float* __restrict__ W1, const float* __restrict__ W2)
{
    __shared__ float2 s[N2];        // 8 KB
    __shared__ float2 tw[N2];       // 8 KB

    const int tid = threadIdx.x;

    if (blockIdx.x >= BATCH) {
        const int wb = blockIdx.x - BATCH;
        if (wb < W1BLKS) {
            const int idx4 = wb * 1024 + tid * 4;
            const int n = idx4 / KF;
            const int k0 = idx4 - n * KF;
            __nv_bfloat16 h[4], l[4];
            #pragma unroll
            for (int j = 0; j < 4; j++) {
                const int k = k0 + j;
                float v;
                if (k == 0)         v = W1[(size_t)n * NFFT];
                else if (k < 1024)  v = W1[(size_t)n * NFFT + k]
                                      + W1[(size_t)n * NFFT + (NFFT - k)];
                else if (k == 1024) v = W1[(size_t)n * NFFT + 1024];
                else                v = 0.f;
                bf_split(v, h[j], l[j]);
            }
            *(uint2*)&g_w_h[idx4] = *(uint2*)h;
            *(uint2*)&g_w_l[idx4] = *(uint2*)l;
        } else {
            const int idx4 = (wb - W1BLKS) * 1024 + tid * 4;
            const int n = idx4 >> 8;
            const int k = idx4 & 255;
            const float4 v = *(const float4*)&W2[idx4];
            __nv_bfloat16 h[4], l[4];
            bf_split(v.x, h[0], l[0]); bf_split(v.y, h[1], l[1]);
            bf_split(v.z, h[2], l[2]); bf_split(v.w, h[3], l[3]);
            const int base = n * K2C + k;
            *(uint2*)&g_w2c[base]       = *(uint2*)h;
            *(uint2*)&g_w2c[base + 256] = *(uint2*)h;
            *(uint2*)&g_w2c[base + 512] = *(uint2*)l;
        }
        return;
    }

    const int b = blockIdx.x;
    const float4* __restrict__ p = (const float4*)x + (size_t)b * (FRAMES * NFFT / 4);

    #pragma unroll
    for (int a = tid; a < N2; a += 256) {
        float sv, cv;
        sincosf(-6.28318530717958647692f * (float)a * (1.0f / N2), &sv, &cv);
        tw[a] = make_float2(cv, sv);
    }

    const float inv = 1.0f / FRAMES;
    #pragma unroll
    for (int h = 0; h < 2; h++) {
        const int f = tid + h * 256;
        float4 acc = make_float4(0.f, 0.f, 0.f, 0.f);
        #pragma unroll
        for (int t = 0; t < FRAMES; t++) {
            float4 v = p[f + t * (NFFT / 4)];
            acc.x += v.x; acc.y += v.y; acc.z += v.z; acc.w += v.w;
        }
        s[rev4_10(2 * f)]     = make_float2(acc.x * inv, acc.y * inv);
        s[rev4_10(2 * f + 1)] = make_float2(acc.z * inv, acc.w * inv);
    }
    __syncthreads();

    #pragma unroll
    for (int st = 0; st < 5; st++) {
        const int q    = 1 << (2 * st);
        const int j    = tid & (q - 1);
        const int blk  = tid >> (2 * st);
        const int base = (blk << (2 * st + 2)) + j;
        const int e    = j << (8 - 2 * st);

        float2 x0 = s[base];
        float2 x1 = s[base + q];
        float2 x2 = s[base + 2 * q];
        float2 x3 = s[base + 3 * q];
        if (e) {
            const float2 w1 = tw[e], w2 = tw[2 * e], w3 = tw[3 * e];
            x1 = make_float2(x1.x * w1.x - x1.y * w1.y, x1.x * w1.y + x1.y * w1.x);
            x2 = make_float2(x2.x * w2.x - x2.y * w2.y, x2.x * w2.y + x2.y * w2.x);
            x3 = make_float2(x3.x * w3.x - x3.y * w3.y, x3.x * w3.y + x3.y * w3.x);
        }
        const float2 ap = make_float2(x0.x + x2.x, x0.y + x2.y);
        const float2 am = make_float2(x0.x - x2.x, x0.y - x2.y);
        const float2 bp = make_float2(x1.x + x3.x, x1.y + x3.y);
        const float2 bm = make_float2(x1.x - x3.x, x1.y - x3.y);
        s[base]         = make_float2(ap.x + bp.x, ap.y + bp.y);
        s[base + q]     = make_float2(am.x + bm.y, am.y - bm.x);
        s[base + 2 * q] = make_float2(ap.x - bp.x, ap.y - bp.y);
        s[base + 3 * q] = make_float2(am.x - bm.y, am.y + bm.x);
        __syncthreads();
    }

    __nv_bfloat16* __restrict__ oh = g_a_h + (size_t)b * KF;
    __nv_bfloat16* __restrict__ ol = g_a_l + (size_t)b * KF;
    #pragma unroll
    for (int k = tid; k <= N2 / 2; k += 256) {
        const float2 zk = s[k];
        const float2 z2 = s[(N2 - k) & (N2 - 1)];
        float un, uc;
        sincosf(3.14159265358979323846f * (float)k * (1.0f / N2), &un, &uc);
        const float sumr = zk.x + z2.x;
        const float sumi = zk.y + z2.y;
        const float difr = zk.x - z2.x;
        float v0 = 0.5f * (sumr + uc * sumi - un * difr);
        float v1 = 0.5f * (sumr - uc * sumi + un * difr);
        __nv_bfloat16 h, l;
        bf_split(v0, h, l); oh[k] = h;       ol[k] = l;
        bf_split(v1, h, l); oh[N2 - k] = h;  ol[N2 - k] = l;
    }
    const __nv_bfloat16 z16 = __float2bfloat16(0.f);
    for (int k = N2 + 1 + tid; k < KF; k += 256) { oh[k] = z16; ol[k] = z16; }
}

// ---------------------------------------------------------------------------
// GEMM1: bf16 mma (hi/lo 3-term), BM=128, BN=128, BK=32, 256 thr, 8 warps.
// ---------------------------------------------------------------------------
__global__ __launch_bounds__(256, 2) void gemm1_mma_kernel(
    const __nv_bfloat16* __restrict__ Ah, const __nv_bfloat16* __restrict__ Al,
    const __nv_bfloat16* __restrict__ Wh, const __nv_bfloat16* __restrict__ Wl)
{
    const int KS = KF, KITERS = 12, KSPL = 3;
    __shared__ __nv_bfloat16 As[2][128 * ASTR];   // 20 KB
    __shared__ __nv_bfloat16 Bs[2][128 * ASTR];   // 20 KB

    const int tid  = threadIdx.x;
    const int wid  = tid >> 5;
    const int lane = tid & 31;
    const int wm0  = (wid & 1) * 64;
    const int wn0  = (wid >> 1) * 32;
    const int m0   = blockIdx.x * 128;
    const int n0   = blockIdx.y * 128;
    const int z    = blockIdx.z;
    const int term = z / KSPL;
    const int kbeg = (z - term * KSPL) * (KITERS * 32);

    const __nv_bfloat16* __restrict__ A = (term == 1) ? Al : Ah;
    const __nv_bfloat16* __restrict__ W = (term == 2) ? Wl : Wh;

    const int a_row = (lane & 7) + ((lane >> 3) & 1) * 8;
    const int a_col = (lane >> 4) * 8;
    const int b_row = ((lane >> 4) & 1) * 8 + (lane & 7);
    const int b_col = ((lane >> 3) & 1) * 8;

    float acc[4][4][4] = {};
    uint4 rA[2], rB[2];

    #pragma unroll
    for (int i = 0; i < 2; i++) {
        const int c   = tid + i * 256;
        const int row = c >> 2;
        const int cc  = (c & 3) * 8;
        *(uint4*)&As[0][row * ASTR + cc] =
            *(const uint4*)&A[(size_t)(m0 + row) * KS + kbeg + cc];
        *(uint4*)&Bs[0][row * ASTR + cc] =
            *(const uint4*)&W[(size_t)(n0 + row) * KS + kbeg + cc];
    }

    #pragma unroll 1
    for (int it = 0; it < KITERS; it++) {
        const int cur = it & 1;
        __syncthreads();
        if (it + 1 < KITERS) {
            const int k0 = kbeg + (it + 1) * 32;
            #pragma unroll
            for (int i = 0; i < 2; i++) {
                const int c   = tid + i * 256;
                const int row = c >> 2;
                const int cc  = (c & 3) * 8;
                rA[i] = *(const uint4*)&A[(size_t)(m0 + row) * KS + k0 + cc];
                rB[i] = *(const uint4*)&W[(size_t)(n0 + row) * KS + k0 + cc];
            }
        }

        const uint32_t baseA = s2u(&As[cur][0]);
        const uint32_t baseB = s2u(&Bs[cur][0]);
        #pragma unroll
        for (int kk = 0; kk < 2; kk++) {
            uint32_t bfr[4][2];
            #pragma unroll
            for (int np = 0; np < 2; np++) {
                uint32_t r0, r1, r2, r3;
                uint32_t addr = baseB +
                    (uint32_t)(((wn0 + np * 16 + b_row) * ASTR + kk * 16 + b_col) * 2);
                ldsm4(r0, r1, r2, r3, addr);
                bfr[np * 2][0] = r0;     bfr[np * 2][1] = r1;
                bfr[np * 2 + 1][0] = r2; bfr[np * 2 + 1][1] = r3;
            }
            #pragma unroll
            for (int mi = 0; mi < 4; mi++) {
                uint32_t afr[4];
                uint32_t addr = baseA +
                    (uint32_t)(((wm0 + mi * 16 + a_row) * ASTR + kk * 16 + a_col) * 2);
                ldsm4(afr[0], afr[1], afr[2], afr[3], addr);
                #pragma unroll
                for (int ni = 0; ni < 4; ni++)
                    mma_bf16(acc[mi][ni], afr, bfr[ni]);
            }
        }

        if (it + 1 < KITERS) {
            const int nxt = cur ^ 1;
            #pragma unroll
            for (int i = 0; i < 2; i++) {
                const int c   = tid + i * 256;
                const int row = c >> 2;
                const int cc  = (c & 3) * 8;
                *(uint4*)&As[nxt][row * ASTR + cc] = rA[i];
                *(uint4*)&Bs[nxt][row * ASTR + cc] = rB[i];
            }
        }
    }

    float* __restrict__ P = g_p1[z];
    const int t4 = lane >> 2;
    const int t2 = (lane & 3) * 2;
    #pragma unroll
    for (int mi = 0; mi < 4; mi++) {
        const int row = m0 + wm0 + mi * 16 + t4;
        #pragma unroll
        for (int ni = 0; ni < 4; ni++) {
            const int col = n0 + wn0 + ni * 8 + t2;
            *(float2*)&P[(size_t)row * HID + col] =
                make_float2(acc[mi][ni][0], acc[mi][ni][1]);
            *(float2*)&P[(size_t)(row + 8) * HID + col] =
                make_float2(acc[mi][ni][2], acc[mi][ni][3]);
        }
    }
}

// ---------------------------------------------------------------------------
// GEMM2: concatenated K=768, chunk 128, split-K 6, single-shot smem load.
// BM=64, BN=64, 128 threads. Whole 64x128 A+B chunk loaded up front (35 KB),
// ONE barrier, then straight-line 8 k-slices of ldsm+mma (no more barriers).
// ---------------------------------------------------------------------------
__global__ __launch_bounds__(128) void gemm2_mma_kernel() {
    __shared__ __nv_bfloat16 As[64 * ASTR2];   // 17.4 KB
    __shared__ __nv_bfloat16 Bs[64 * ASTR2];   // 17.4 KB

    const int tid  = threadIdx.x;
    const int wid  = tid >> 5;
    const int lane = tid & 31;
    const int wm0  = (wid & 1) * 32;
    const int wn0  = (wid >> 1) * 32;
    const int m0   = blockIdx.x * 64;
    const int n0   = blockIdx.y * 64;
    const int kbeg = blockIdx.z * 128;

    const int a_row = (lane & 7) + ((lane >> 3) & 1) * 8;
    const int a_col = (lane >> 4) * 8;
    const int b_row = ((lane >> 4) & 1) * 8 + (lane & 7);
    const int b_col = ((lane >> 3) & 1) * 8;

    // single-shot fill: 1024 uint4 per array, 8 per thread each
    #pragma unroll
    for (int i = 0; i < 8; i++) {
        const int c   = tid + i * 128;        // 0..1023
        const int row = c >> 4;
        const int cc  = (c & 15) * 8;
        *(uint4*)&As[row * ASTR2 + cc] =
            *(const uint4*)&g_h1c[(size_t)(m0 + row) * K2C + kbeg + cc];
        *(uint4*)&Bs[row * ASTR2 + cc] =
            *(const uint4*)&g_w2c[(size_t)(n0 + row) * K2C + kbeg + cc];
    }
    __syncthreads();

    float acc[2][4][4] = {};
    const uint32_t baseA = s2u(&As[0]);
    const uint32_t baseB = s2u(&Bs[0]);

    #pragma unroll
    for (int sl = 0; sl < 8; sl++) {          // 8 x k16 slices, no barriers
        const int kc = sl * 16;
        uint32_t bfr[4][2];
        #pragma unroll
        for (int np = 0; np < 2; np++) {
            uint32_t r0, r1, r2, r3;
            uint32_t addr = baseB +
                (uint32_t)(((wn0 + np * 16 + b_row) * ASTR2 + kc + b_col) * 2);
            ldsm4(r0, r1, r2, r3, addr);
            bfr[np * 2][0] = r0;     bfr[np * 2][1] = r1;
            bfr[np * 2 + 1][0] = r2; bfr[np * 2 + 1][1] = r3;
        }
        #pragma unroll
        for (int mi = 0; mi < 2; mi++) {
            uint32_t afr[4];
            uint32_t addr = baseA +
                (uint32_t)(((wm0 + mi * 16 + a_row) * ASTR2 + kc + a_col) * 2);
            ldsm4(afr[0], afr[1], afr[2], afr[3], addr);
            #pragma unroll
            for (int ni = 0; ni < 4; ni++)
                mma_bf16(acc[mi][ni], afr, bfr[ni]);
        }
    }

    float* __restrict__ P = g_p2[blockIdx.z];
    const int t4 = lane >> 2;
    const int t2 = (lane & 3) * 2;
    #pragma unroll
    for (int mi = 0; mi < 2; mi++) {
        const int row = m0 + wm0 + mi * 16 + t4;
        #pragma unroll
        for (int ni = 0; ni < 4; ni++) {
            const int col = n0 + wn0 + ni * 8 + t2;
            *(float2*)&P[(size_t)row * HID + col] =
                make_float2(acc[mi][ni][0], acc[mi][ni][1]);
            *(float2*)&P[(size_t)(row + 8) * HID + col] =
                make_float2(acc[mi][ni][2], acc[mi][ni][3]);
        }
    }
}

// ---------------------------------------------------------------------------
// Reduce gemm1 partials + bias + relu -> h1cat [h | l | h].  float2/thread.
// ---------------------------------------------------------------------------
__global__ __launch_bounds__(256) void reduce1_kernel(const float* __restrict__ bias) {
    const int i2 = blockIdx.x * 256 + threadIdx.x;     // 0 .. 131071
    const int n2 = i2 & (HID / 2 - 1);
    const int row = i2 >> 7;
    float2 v = ((const float2*)bias)[n2];
    #pragma unroll
    for (int zz = 0; zz < NZ1; zz++) {
        const float2 pv = *(const float2*)&g_p1[zz][i2 * 2];
        v.x += pv.x; v.y += pv.y;
    }
    v.x = fmaxf(v.x, 0.f);
    v.y = fmaxf(v.y, 0.f);
    __nv_bfloat16 h[2], l[2];
    bf_split(v.x, h[0], l[0]);
    bf_split(v.y, h[1], l[1]);
    const int base = row * K2C + n2 * 2;
    *(uint32_t*)&g_h1c[base]       = *(uint32_t*)h;
    *(uint32_t*)&g_h1c[base + 256] = *(uint32_t*)l;
    *(uint32_t*)&g_h1c[base + 512] = *(uint32_t*)h;
}

// ---------------------------------------------------------------------------
// Fused: reduce gemm2 partials (6) + bias + relu + dot(W3) + sigmoid -> out.
// ---------------------------------------------------------------------------
__global__ __launch_bounds__(256) void reduce2_out_kernel(
    const float* __restrict__ b2, const float* __restrict__ W3,
    const float* __restrict__ b3, float* __restrict__ out)
{
    const int warp = threadIdx.x >> 5;
    const int lane = threadIdx.x & 31;
    const int b    = blockIdx.x * 8 + warp;
    const int base = b * HID + lane * 8;

    float s = 0.f;
    #pragma unroll
    for (int half = 0; half < 2; half++) {
        const int off = base + half * 4;
        const int coff = lane * 8 + half * 4;
        float4 v  = *(const float4*)&b2[coff];
        #pragma unroll
        for (int zz = 0; zz < NZ2; zz++) {
            const float4 pv = *(const float4*)&g_p2[zz][off];
            v.x += pv.x; v.y += pv.y; v.z += pv.z; v.w += pv.w;
        }
        const float4 w = *(const float4*)&W3[coff];
        s += fmaxf(v.x, 0.f) * w.x + fmaxf(v.y, 0.f) * w.y
           + fmaxf(v.z, 0.f) * w.z + fmaxf(v.w, 0.f) * w.w;
    }
    #pragma unroll
    for (int off = 16; off; off >>= 1) s += __shfl_down_sync(0xffffffffu, s, off);
    if (lane == 0) out[b] = 1.f / (1.f + expf(-(s + b3[0])));
}

// ---------------------------------------------------------------------------
extern "C" void kernel_launch(void* const* d_in, const int* in_sizes, int n_in,
                              void* d_out, int out_size)
{
    const float* x  = (const float*)d_in[0];
    const float* W1 = (const float*)d_in[1];
    const float* b1 = (const float*)d_in[2];
    const float* W2 = (const float*)d_in[3];
    const float* b2 = (const float*)d_in[4];
    const float* W3 = (const float*)d_in[5];
    const float* b3 = (const float*)d_in[6];
    float* out = (float*)d_out;

    __nv_bfloat16 *p_ah, *p_al, *p_wh, *p_wl;
    cudaGetSymbolAddress((void**)&p_ah, g_a_h);
    cudaGetSymbolAddress((void**)&p_al, g_a_l);
    cudaGetSymbolAddress((void**)&p_wh, g_w_h);
    cudaGetSymbolAddress((void**)&p_wl, g_w_l);

    // launch 1: FFT rows (1024 blocks) + W1 fold/split (288) + W2 split/cat (64)
    fftmean_prep_kernel<<<BATCH + W1BLKS + W2BLKS, 256>>>(x, W1, W2);

    // launch 2: gemm1 (K=1152, 3 terms x 3 chunks)
    dim3 g1(BATCH / 128, HID / 128, NZ1);    // (8, 2, 9) = 144 CTAs
    gemm1_mma_kernel<<<g1, 256>>>(p_ah, p_al, p_wh, p_wl);

    // launch 3: reduce1 -> h1cat
    reduce1_kernel<<<BATCH * HID / 2 / 256, 256>>>(b1);

    // launch 4: gemm2 (K=768 concat, split-K 6, single-shot smem) = 384 CTAs
    dim3 g2(BATCH / 64, HID / 64, NZ2);
    gemm2_mma_kernel<<<g2, 128>>>();

    // launch 5: reduce2 + dot(W3) + sigmoid
    reduce2_out_kernel<<<BATCH / 8, 256>>>(b2, W3, b3, out);
}